// round 8
// baseline (speedup 1.0000x reference)
#include <cuda_runtime.h>
#include <math.h>

#define CIN 64
#define HW  256
#define HO  128
#define NB  16

// ---------------- device scratch (no allocations allowed) ----------------
__device__ float g_pooled[NB * CIN];
__device__ int   g_selidx[NB * 2];
__device__ float g_selwt [NB * 2];
__device__ int   g_sched [NB * 2];   // block order: heavy experts first
__device__ float g_bnA[4 * 64];
__device__ float g_bnB[4 * 64];
// transposed weights [e][cin][kh][kw][cout], cout minor
// sizes: e0 36864, e1 102400, e2 200704, e3 331776 -> total 671744
__device__ float g_wT[671744];

// ---------------- launch #1: global average pool, one block per (b,c) plane ----
__global__ void pool_kernel(const float* __restrict__ x) {
    __shared__ float red[256];
    int tid = threadIdx.x;
    const float4* xp = (const float4*)(x + (size_t)blockIdx.x * (HW * HW));
    float s = 0.f;
    for (int i = tid; i < HW * HW / 4; i += 256) {
        float4 v = xp[i];
        s += (v.x + v.y) + (v.z + v.w);
    }
    red[tid] = s;
    __syncthreads();
    for (int off = 128; off > 0; off >>= 1) {
        if (tid < off) red[tid] += red[tid + off];
        __syncthreads();
    }
    if (tid == 0) g_pooled[blockIdx.x] = red[0] * (1.f / (HW * HW));
}

// ---------------- launch #2: ALL weight transposes in one kernel ----------------
__device__ __forceinline__ void twk_one(const float* __restrict__ w, int off, int KK, int i) {
    int cout = i & 63;
    int row  = i >> 6;
    int cin  = row / KK;
    int kidx = row - cin * KK;
    g_wT[off + i] = w[(cout * 64 + cin) * KK + kidx];
}

__global__ void twk_all_kernel(const float* __restrict__ w0, const float* __restrict__ w1,
                               const float* __restrict__ w2, const float* __restrict__ w3) {
    int i = blockIdx.x * 256 + threadIdx.x;
    if (i < 36864)       twk_one(w0, 0,      9,  i);
    else if (i < 139264) twk_one(w1, 36864,  25, i - 36864);
    else if (i < 339968) twk_one(w2, 139264, 49, i - 139264);
    else if (i < 671744) twk_one(w3, 339968, 81, i - 339968);
}

// ---------------- launch #3: gate (softmax + top-2 + schedule) AND bn fold ------
__global__ void gatebn_kernel(const float* __restrict__ gw, const float* __restrict__ gb,
                              const float* __restrict__ sc, const float* __restrict__ bi,
                              const float* __restrict__ me, const float* __restrict__ va,
                              const float* __restrict__ b0, const float* __restrict__ b1,
                              const float* __restrict__ b2, const float* __restrict__ b3) {
    __shared__ int s_idx[NB * 2];
    int t = threadIdx.x;

    // BN fold: y = conv*A + B  (256 threads = 4 experts x 64 couts)
    {
        const float* bb = (t < 64) ? b0 : (t < 128) ? b1 : (t < 192) ? b2 : b3;
        float inv = sc[t] * rsqrtf(va[t] + 1e-5f);
        g_bnA[t] = inv;
        g_bnB[t] = bb[t & 63] * inv + bi[t] - me[t] * inv;
    }

    // Gate (threads 0..15, one per batch)
    if (t < NB) {
        int b = t;
        float lg[4];
        for (int e = 0; e < 4; ++e) {
            float s = gb[e];
            for (int c = 0; c < CIN; ++c) s += g_pooled[b * CIN + c] * gw[e * CIN + c];
            lg[e] = s;
        }
        float m = fmaxf(fmaxf(lg[0], lg[1]), fmaxf(lg[2], lg[3]));
        float p[4];
        float Z = 0.f;
        for (int e = 0; e < 4; ++e) { p[e] = expf(lg[e] - m); Z += p[e]; }
        for (int e = 0; e < 4; ++e) p[e] /= Z;
        int i0 = 0;
        for (int e = 1; e < 4; ++e) if (p[e] > p[i0]) i0 = e;   // strict >, lower idx wins ties
        int i1 = -1;
        for (int e = 0; e < 4; ++e) {
            if (e == i0) continue;
            if (i1 < 0 || p[e] > p[i1]) i1 = e;
        }
        float den = p[i0] + p[i1] + 1e-8f;
        g_selidx[b * 2 + 0] = i0; g_selwt[b * 2 + 0] = p[i0] / den;
        g_selidx[b * 2 + 1] = i1; g_selwt[b * 2 + 1] = p[i1] / den;
        s_idx[b * 2 + 0] = i0;
        s_idx[b * 2 + 1] = i1;
    }
    __syncthreads();
    if (t == 0) {
        // stable counting sort, heaviest expert (largest K) first
        int n = 0;
        for (int e = 3; e >= 0; --e)
            for (int z = 0; z < NB * 2; ++z)
                if (s_idx[z] == e) g_sched[n++] = z;
    }
}

// ---------------- launch #4: merged expert conv + BN + GELU, packed f32x2 FMA ---
// BARRIER-FREE, GMEM-WEIGHT LAYOUT:
// 256 threads = 32(ow) x 4(cout-quarter: 16 couts) x 2(row-pair group).
// Each thread: 4 oh-rows x 16 couts => 4x8 u64 acc (64 regs) -> 2 blocks/SM.
// Weights read via warp-uniform __ldg LDG.128 (L1 broadcast): each 16B load
// feeds 8 FFMA2 (4 pixels x 2 cout-pairs). No shared memory, no syncthreads.
// x loads batched in kw-chunks of C to bound register pressure.
template <int E, int K, int D, int C, int WOFF>
__device__ __forceinline__ void conv_body(const float* __restrict__ xb,
                                          float* __restrict__ out,
                                          int z, int tid) {
    const int pad = D * (K - 1) / 2;
    const int owl = tid & 31;
    const int chq = (tid >> 5) & 3;              // 4 groups of 16 couts
    const int ohq = tid >> 7;                    // 2 groups of 4 rows
    const int ow  = blockIdx.x * 32 + owl;
    const int oh0 = blockIdx.y * 8 + ohq * 4;    // 4 rows per thread
    const int ows = 2 * ow - pad;

    int ohs[4];
    unsigned rmask[4];
#pragma unroll
    for (int p = 0; p < 4; ++p) {
        ohs[p] = 2 * (oh0 + p) - pad;
        unsigned m = 0;
#pragma unroll
        for (int k = 0; k < K; ++k)
            if ((unsigned)(ohs[p] + D * k) < (unsigned)HW) m |= 1u << k;
        rmask[p] = m;
    }
    unsigned cmask = 0;
#pragma unroll
    for (int k = 0; k < K; ++k)
        if ((unsigned)(ows + D * k) < (unsigned)HW) cmask |= 1u << k;

    unsigned long long acc[4][8];
#pragma unroll
    for (int p = 0; p < 4; ++p)
#pragma unroll
        for (int r = 0; r < 8; ++r) acc[p][r] = 0ULL;

    const float* wbase = g_wT + WOFF + chq * 16;

#pragma unroll 1
    for (int cin = 0; cin < CIN; ++cin) {
        const float* xp = xb + (size_t)cin * (HW * HW);
#pragma unroll 1
        for (int kh = 0; kh < K; ++kh) {
            const float* xr[4];
            bool rv[4];
#pragma unroll
            for (int p = 0; p < 4; ++p) {
                xr[p] = xp + (ohs[p] + D * kh) * HW + ows;
                rv[p] = (rmask[p] >> kh) & 1;
            }
            const float* wk = wbase + (size_t)((cin * K + kh) * K) * 64;
#pragma unroll
            for (int kw0 = 0; kw0 < K; kw0 += C) {
                // ---- batched x loads for this kw chunk (high MLP) ----
                float xv[4 * C];
#pragma unroll
                for (int p = 0; p < 4; ++p)
#pragma unroll
                    for (int c = 0; c < C; ++c) {
                        if (kw0 + c < K) {
                            float v = 0.f;
                            if (rv[p] && ((cmask >> (kw0 + c)) & 1))
                                v = __ldg(xr[p] + D * (kw0 + c));
                            xv[p * C + c] = v;
                        }
                    }
                // ---- warp-uniform weight LDG.128 + FFMA2 ----
#pragma unroll
                for (int c = 0; c < C; ++c) {
                    if (kw0 + c < K) {
                        unsigned long long x2[4];
#pragma unroll
                        for (int p = 0; p < 4; ++p)
                            asm("mov.b64 %0, {%1, %1};" : "=l"(x2[p])
                                : "r"(__float_as_uint(xv[p * C + c])));
                        const ulonglong2* wq =
                            (const ulonglong2*)(wk + (kw0 + c) * 64);
#pragma unroll
                        for (int q = 0; q < 4; ++q) {
                            ulonglong2 wv = __ldg(wq + q);
#pragma unroll
                            for (int p = 0; p < 4; ++p) {
                                asm("fma.rn.f32x2 %0, %1, %2, %0;"
                                    : "+l"(acc[p][2 * q + 0]) : "l"(x2[p]), "l"(wv.x));
                                asm("fma.rn.f32x2 %0, %1, %2, %0;"
                                    : "+l"(acc[p][2 * q + 1]) : "l"(x2[p]), "l"(wv.y));
                            }
                        }
                    }
                }
            }
        }
    }

    // epilogue: BN fold + exact GELU + gate weight; stores coalesced along ow
    const float wt = g_selwt[z];
    const int b = z >> 1, s = z & 1;
#pragma unroll
    for (int p = 0; p < 4; ++p) {
        float* ob = out + ((size_t)b * 128 + s * 64 + chq * 16) * (HO * HO)
                  + (oh0 + p) * HO + ow;
#pragma unroll
        for (int r = 0; r < 8; ++r) {
            unsigned u0, u1;
            asm("mov.b64 {%0, %1}, %2;" : "=r"(u0), "=r"(u1) : "l"(acc[p][r]));
            float v0 = __uint_as_float(u0);
            float v1 = __uint_as_float(u1);
            const int c0 = chq * 16 + 2 * r, c1 = c0 + 1;
            float y0 = v0 * g_bnA[E * 64 + c0] + g_bnB[E * 64 + c0];
            float y1 = v1 * g_bnA[E * 64 + c1] + g_bnB[E * 64 + c1];
            y0 = 0.5f * y0 * (1.f + erff(y0 * 0.70710678118654752f));
            y1 = 0.5f * y1 * (1.f + erff(y1 * 0.70710678118654752f));
            ob[(size_t)(2 * r) * (HO * HO)]     = y0 * wt;
            ob[(size_t)(2 * r + 1) * (HO * HO)] = y1 * wt;
        }
    }
}

__global__ void __launch_bounds__(256, 2)
conv_all_kernel(const float* __restrict__ x, float* __restrict__ out) {
    const int z = g_sched[blockIdx.z];          // heavy-first schedule
    const int tid = threadIdx.x;
    const float* xb = x + (size_t)(z >> 1) * CIN * HW * HW;
    const int e = g_selidx[z];
    if (e == 0)      conv_body<0, 3, 1, 3, 0     >(xb, out, z, tid);
    else if (e == 1) conv_body<1, 5, 2, 5, 36864 >(xb, out, z, tid);
    else if (e == 2) conv_body<2, 7, 3, 7, 139264>(xb, out, z, tid);
    else             conv_body<3, 9, 4, 5, 339968>(xb, out, z, tid);
}

// ---------------- launch: exactly 4 launches, conv is #4 (ncu capture slot) -----
extern "C" void kernel_launch(void* const* d_in, const int* in_sizes, int n_in,
                              void* d_out, int out_size) {
    (void)in_sizes; (void)n_in; (void)out_size;
    const float* x   = (const float*)d_in[0];
    const float* w0  = (const float*)d_in[1];
    const float* b0  = (const float*)d_in[2];
    const float* w1  = (const float*)d_in[3];
    const float* b1  = (const float*)d_in[4];
    const float* w2  = (const float*)d_in[5];
    const float* b2  = (const float*)d_in[6];
    const float* w3  = (const float*)d_in[7];
    const float* b3  = (const float*)d_in[8];
    const float* bns = (const float*)d_in[9];
    const float* bnb = (const float*)d_in[10];
    const float* bnm = (const float*)d_in[11];
    const float* bnv = (const float*)d_in[12];
    const float* gw  = (const float*)d_in[13];
    const float* gb  = (const float*)d_in[14];
    float* out = (float*)d_out;

    pool_kernel<<<NB * CIN, 256>>>(x);                               // #1
    twk_all_kernel<<<(671744 + 255) / 256, 256>>>(w0, w1, w2, w3);   // #2
    gatebn_kernel<<<1, 256>>>(gw, gb, bns, bnb, bnm, bnv,
                              b0, b1, b2, b3);                       // #3
    dim3 grid(4, 16, NB * 2);  // 128/32 ow-tiles x 128/8 oh-tiles x (b,slot)
    conv_all_kernel<<<grid, 256>>>(x, out);                          // #4
}

// round 9
// speedup vs baseline: 1.2308x; 1.2308x over previous
#include <cuda_runtime.h>
#include <math.h>

#define CIN 64
#define HW  256
#define HO  128
#define NB  16

// ---------------- device scratch (no allocations allowed) ----------------
__device__ float g_pooled[NB * CIN];
__device__ int   g_selidx[NB * 2];
__device__ float g_selwt [NB * 2];
__device__ int   g_sched [NB * 2];   // block order: heavy experts first
__device__ float g_bnA[4 * 64];
__device__ float g_bnB[4 * 64];
// transposed weights [e][cin][kh][kw][cout], cout minor
// sizes: e0 36864, e1 102400, e2 200704, e3 331776 -> total 671744
__device__ float g_wT[671744];

// ---------------- launch #1: global average pool, one block per (b,c) plane ----
__global__ void pool_kernel(const float* __restrict__ x) {
    __shared__ float red[256];
    int tid = threadIdx.x;
    const float4* xp = (const float4*)(x + (size_t)blockIdx.x * (HW * HW));
    float s = 0.f;
    for (int i = tid; i < HW * HW / 4; i += 256) {
        float4 v = xp[i];
        s += (v.x + v.y) + (v.z + v.w);
    }
    red[tid] = s;
    __syncthreads();
    for (int off = 128; off > 0; off >>= 1) {
        if (tid < off) red[tid] += red[tid + off];
        __syncthreads();
    }
    if (tid == 0) g_pooled[blockIdx.x] = red[0] * (1.f / (HW * HW));
}

// ---------------- launch #2: ALL weight transposes in one kernel ----------------
__device__ __forceinline__ void twk_one(const float* __restrict__ w, int off, int KK, int i) {
    int cout = i & 63;
    int row  = i >> 6;
    int cin  = row / KK;
    int kidx = row - cin * KK;
    g_wT[off + i] = w[(cout * 64 + cin) * KK + kidx];
}

__global__ void twk_all_kernel(const float* __restrict__ w0, const float* __restrict__ w1,
                               const float* __restrict__ w2, const float* __restrict__ w3) {
    int i = blockIdx.x * 256 + threadIdx.x;
    if (i < 36864)       twk_one(w0, 0,      9,  i);
    else if (i < 139264) twk_one(w1, 36864,  25, i - 36864);
    else if (i < 339968) twk_one(w2, 139264, 49, i - 139264);
    else if (i < 671744) twk_one(w3, 339968, 81, i - 339968);
}

// ---------------- launch #3: gate (softmax + top-2 + schedule) AND bn fold ------
__global__ void gatebn_kernel(const float* __restrict__ gw, const float* __restrict__ gb,
                              const float* __restrict__ sc, const float* __restrict__ bi,
                              const float* __restrict__ me, const float* __restrict__ va,
                              const float* __restrict__ b0, const float* __restrict__ b1,
                              const float* __restrict__ b2, const float* __restrict__ b3) {
    __shared__ int s_idx[NB * 2];
    int t = threadIdx.x;

    // BN fold: y = conv*A + B  (256 threads = 4 experts x 64 couts)
    {
        const float* bb = (t < 64) ? b0 : (t < 128) ? b1 : (t < 192) ? b2 : b3;
        float inv = sc[t] * rsqrtf(va[t] + 1e-5f);
        g_bnA[t] = inv;
        g_bnB[t] = bb[t & 63] * inv + bi[t] - me[t] * inv;
    }

    // Gate (threads 0..15, one per batch)
    if (t < NB) {
        int b = t;
        float lg[4];
        for (int e = 0; e < 4; ++e) {
            float s = gb[e];
            for (int c = 0; c < CIN; ++c) s += g_pooled[b * CIN + c] * gw[e * CIN + c];
            lg[e] = s;
        }
        float m = fmaxf(fmaxf(lg[0], lg[1]), fmaxf(lg[2], lg[3]));
        float p[4];
        float Z = 0.f;
        for (int e = 0; e < 4; ++e) { p[e] = expf(lg[e] - m); Z += p[e]; }
        for (int e = 0; e < 4; ++e) p[e] /= Z;
        int i0 = 0;
        for (int e = 1; e < 4; ++e) if (p[e] > p[i0]) i0 = e;   // strict >, lower idx wins ties
        int i1 = -1;
        for (int e = 0; e < 4; ++e) {
            if (e == i0) continue;
            if (i1 < 0 || p[e] > p[i1]) i1 = e;
        }
        float den = p[i0] + p[i1] + 1e-8f;
        g_selidx[b * 2 + 0] = i0; g_selwt[b * 2 + 0] = p[i0] / den;
        g_selidx[b * 2 + 1] = i1; g_selwt[b * 2 + 1] = p[i1] / den;
        s_idx[b * 2 + 0] = i0;
        s_idx[b * 2 + 1] = i1;
    }
    __syncthreads();
    if (t == 0) {
        // stable counting sort, heaviest expert (largest K) first
        int n = 0;
        for (int e = 3; e >= 0; --e)
            for (int z = 0; z < NB * 2; ++z)
                if (s_idx[z] == e) g_sched[n++] = z;
    }
}

// ---------------- launch #4: merged expert conv + BN + GELU, packed f32x2 FMA ---
// OCC-2 + 8:1 REUSE LAYOUT: 256 threads = 32(ow) x 4(cout-quarter:16 couts)
// x 2(row groups). Each thread: 4 oh-rows x 16 couts => 4x8 u64 acc (64 regs)
// -> 2 blocks/SM. Weights staged in smem; per tap each thread does
// 4 broadcast LDS.128 feeding 32 FFMA2 (8:1). x loads batched in kw-chunks.
template <int E, int K, int D, int CHUNK, int C, int WOFF>
__device__ __forceinline__ void conv_body(const float* __restrict__ xb,
                                          float* __restrict__ out,
                                          int z, int tid, float4* sw4) {
    const int pad = D * (K - 1) / 2;
    const int owl = tid & 31;
    const int chq = (tid >> 5) & 3;              // 4 groups of 16 couts
    const int ohq = tid >> 7;                    // 2 groups of 4 rows
    const int ow  = blockIdx.x * 32 + owl;
    const int oh0 = blockIdx.y * 8 + ohq * 4;    // 4 rows per thread
    const int ows = 2 * ow - pad;

    int ohs[4];
    unsigned rmask[4];
#pragma unroll
    for (int p = 0; p < 4; ++p) {
        ohs[p] = 2 * (oh0 + p) - pad;
        unsigned m = 0;
#pragma unroll
        for (int k = 0; k < K; ++k)
            if ((unsigned)(ohs[p] + D * k) < (unsigned)HW) m |= 1u << k;
        rmask[p] = m;
    }
    unsigned cmask = 0;
#pragma unroll
    for (int k = 0; k < K; ++k)
        if ((unsigned)(ows + D * k) < (unsigned)HW) cmask |= 1u << k;

    unsigned long long acc[4][8];
#pragma unroll
    for (int p = 0; p < 4; ++p)
#pragma unroll
        for (int r = 0; r < 8; ++r) acc[p][r] = 0ULL;

    float* sw = (float*)sw4;
    const float4* wsrc = (const float4*)(g_wT + WOFF);

    for (int cc = 0; cc < CIN; cc += CHUNK) {
        __syncthreads();
        for (int i = tid; i < CHUNK * K * K * 16; i += 256)
            sw4[i] = wsrc[cc * (K * K * 16) + i];
        __syncthreads();

#pragma unroll 1
        for (int cl = 0; cl < CHUNK; ++cl) {
            const float* xp = xb + (size_t)(cc + cl) * (HW * HW);
#pragma unroll 1
            for (int kh = 0; kh < K; ++kh) {
                const float* xr[4];
                bool rv[4];
#pragma unroll
                for (int p = 0; p < 4; ++p) {
                    xr[p] = xp + (ohs[p] + D * kh) * HW + ows;
                    rv[p] = (rmask[p] >> kh) & 1;
                }
                const float* wk = sw + ((cl * K + kh) * K) * 64 + chq * 16;
#pragma unroll
                for (int kw0 = 0; kw0 < K; kw0 += C) {
                    // ---- batched x loads for this kw chunk (high MLP) ----
                    float xv[4 * C];
#pragma unroll
                    for (int p = 0; p < 4; ++p)
#pragma unroll
                        for (int c = 0; c < C; ++c) {
                            if (kw0 + c < K) {
                                float v = 0.f;
                                if (rv[p] && ((cmask >> (kw0 + c)) & 1))
                                    v = __ldg(xr[p] + D * (kw0 + c));
                                xv[p * C + c] = v;
                            }
                        }
                    // ---- broadcast LDS.128 + FFMA2 (8 per LDS) ----
#pragma unroll
                    for (int c = 0; c < C; ++c) {
                        if (kw0 + c < K) {
                            unsigned long long x2[4];
#pragma unroll
                            for (int p = 0; p < 4; ++p)
                                asm("mov.b64 %0, {%1, %1};" : "=l"(x2[p])
                                    : "r"(__float_as_uint(xv[p * C + c])));
                            const ulonglong2* wq =
                                (const ulonglong2*)(wk + (kw0 + c) * 64);
#pragma unroll
                            for (int q = 0; q < 4; ++q) {
                                ulonglong2 wv = wq[q];
#pragma unroll
                                for (int p = 0; p < 4; ++p) {
                                    asm("fma.rn.f32x2 %0, %1, %2, %0;"
                                        : "+l"(acc[p][2 * q + 0]) : "l"(x2[p]), "l"(wv.x));
                                    asm("fma.rn.f32x2 %0, %1, %2, %0;"
                                        : "+l"(acc[p][2 * q + 1]) : "l"(x2[p]), "l"(wv.y));
                                }
                            }
                        }
                    }
                }
            }
        }
    }

    // epilogue: BN fold + exact GELU + gate weight; stores coalesced along ow
    const float wt = g_selwt[z];
    const int b = z >> 1, s = z & 1;
#pragma unroll
    for (int p = 0; p < 4; ++p) {
        float* ob = out + ((size_t)b * 128 + s * 64 + chq * 16) * (HO * HO)
                  + (oh0 + p) * HO + ow;
#pragma unroll
        for (int r = 0; r < 8; ++r) {
            unsigned u0, u1;
            asm("mov.b64 {%0, %1}, %2;" : "=r"(u0), "=r"(u1) : "l"(acc[p][r]));
            float v0 = __uint_as_float(u0);
            float v1 = __uint_as_float(u1);
            const int c0 = chq * 16 + 2 * r, c1 = c0 + 1;
            float y0 = v0 * g_bnA[E * 64 + c0] + g_bnB[E * 64 + c0];
            float y1 = v1 * g_bnA[E * 64 + c1] + g_bnB[E * 64 + c1];
            y0 = 0.5f * y0 * (1.f + erff(y0 * 0.70710678118654752f));
            y1 = 0.5f * y1 * (1.f + erff(y1 * 0.70710678118654752f));
            ob[(size_t)(2 * r) * (HO * HO)]     = y0 * wt;
            ob[(size_t)(2 * r + 1) * (HO * HO)] = y1 * wt;
        }
    }
}

__global__ void __launch_bounds__(256, 2)
conv_all_kernel(const float* __restrict__ x, float* __restrict__ out) {
    __shared__ float4 sw4[2592];   // max: E3 CHUNK=2 -> 2*81*64 floats = 41472 B
    const int z = g_sched[blockIdx.z];          // heavy-first schedule
    const int tid = threadIdx.x;
    const float* xb = x + (size_t)(z >> 1) * CIN * HW * HW;
    const int e = g_selidx[z];
    if (e == 0)      conv_body<0, 3, 1, 16, 3, 0     >(xb, out, z, tid, sw4);
    else if (e == 1) conv_body<1, 5, 2, 4,  5, 36864 >(xb, out, z, tid, sw4);
    else if (e == 2) conv_body<2, 7, 3, 2,  4, 139264>(xb, out, z, tid, sw4);
    else             conv_body<3, 9, 4, 2,  3, 339968>(xb, out, z, tid, sw4);
}

// ---------------- launch: exactly 4 launches, conv is #4 (ncu capture slot) -----
extern "C" void kernel_launch(void* const* d_in, const int* in_sizes, int n_in,
                              void* d_out, int out_size) {
    (void)in_sizes; (void)n_in; (void)out_size;
    const float* x   = (const float*)d_in[0];
    const float* w0  = (const float*)d_in[1];
    const float* b0  = (const float*)d_in[2];
    const float* w1  = (const float*)d_in[3];
    const float* b1  = (const float*)d_in[4];
    const float* w2  = (const float*)d_in[5];
    const float* b2  = (const float*)d_in[6];
    const float* w3  = (const float*)d_in[7];
    const float* b3  = (const float*)d_in[8];
    const float* bns = (const float*)d_in[9];
    const float* bnb = (const float*)d_in[10];
    const float* bnm = (const float*)d_in[11];
    const float* bnv = (const float*)d_in[12];
    const float* gw  = (const float*)d_in[13];
    const float* gb  = (const float*)d_in[14];
    float* out = (float*)d_out;

    pool_kernel<<<NB * CIN, 256>>>(x);                               // #1
    twk_all_kernel<<<(671744 + 255) / 256, 256>>>(w0, w1, w2, w3);   // #2
    gatebn_kernel<<<1, 256>>>(gw, gb, bns, bnb, bnm, bnv,
                              b0, b1, b2, b3);                       // #3
    dim3 grid(4, 16, NB * 2);  // 128/32 ow-tiles x 128/8 oh-tiles x (b,slot)
    conv_all_kernel<<<grid, 256>>>(x, out);                          // #4
}

// round 10
// speedup vs baseline: 1.3703x; 1.1134x over previous
#include <cuda_runtime.h>
#include <math.h>

#define CIN 64
#define HW  256
#define HO  128
#define NB  16

// ---------------- device scratch (no allocations allowed) ----------------
__device__ float g_pooled[NB * CIN];
__device__ int   g_selidx[NB * 2];
__device__ float g_selwt [NB * 2];
__device__ int   g_sched [NB * 2];   // block order: heavy experts first
__device__ float g_bnA[4 * 64];
__device__ float g_bnB[4 * 64];
// transposed weights [e][cin][kh][kw][cout], cout minor
// sizes: e0 36864, e1 102400, e2 200704, e3 331776 -> total 671744
__device__ float g_wT[671744];
// zero page: out-of-bounds taps point here (covers cl*65536 offsets, CHUNK<=16)
__device__ float g_zero[1048576];    // 4 MB, zero-initialized at module load

// ---------------- launch #1: global average pool, one block per (b,c) plane ----
__global__ void pool_kernel(const float* __restrict__ x) {
    __shared__ float red[256];
    int tid = threadIdx.x;
    const float4* xp = (const float4*)(x + (size_t)blockIdx.x * (HW * HW));
    float s = 0.f;
    for (int i = tid; i < HW * HW / 4; i += 256) {
        float4 v = xp[i];
        s += (v.x + v.y) + (v.z + v.w);
    }
    red[tid] = s;
    __syncthreads();
    for (int off = 128; off > 0; off >>= 1) {
        if (tid < off) red[tid] += red[tid + off];
        __syncthreads();
    }
    if (tid == 0) g_pooled[blockIdx.x] = red[0] * (1.f / (HW * HW));
}

// ---------------- launch #2: ALL weight transposes in one kernel ----------------
__device__ __forceinline__ void twk_one(const float* __restrict__ w, int off, int KK, int i) {
    int cout = i & 63;
    int row  = i >> 6;
    int cin  = row / KK;
    int kidx = row - cin * KK;
    g_wT[off + i] = w[(cout * 64 + cin) * KK + kidx];
}

__global__ void twk_all_kernel(const float* __restrict__ w0, const float* __restrict__ w1,
                               const float* __restrict__ w2, const float* __restrict__ w3) {
    int i = blockIdx.x * 256 + threadIdx.x;
    if (i < 36864)       twk_one(w0, 0,      9,  i);
    else if (i < 139264) twk_one(w1, 36864,  25, i - 36864);
    else if (i < 339968) twk_one(w2, 139264, 49, i - 139264);
    else if (i < 671744) twk_one(w3, 339968, 81, i - 339968);
}

// ---------------- launch #3: gate (softmax + top-2 + schedule) AND bn fold ------
__global__ void gatebn_kernel(const float* __restrict__ gw, const float* __restrict__ gb,
                              const float* __restrict__ sc, const float* __restrict__ bi,
                              const float* __restrict__ me, const float* __restrict__ va,
                              const float* __restrict__ b0, const float* __restrict__ b1,
                              const float* __restrict__ b2, const float* __restrict__ b3) {
    __shared__ int s_idx[NB * 2];
    int t = threadIdx.x;

    // BN fold: y = conv*A + B  (256 threads = 4 experts x 64 couts)
    {
        const float* bb = (t < 64) ? b0 : (t < 128) ? b1 : (t < 192) ? b2 : b3;
        float inv = sc[t] * rsqrtf(va[t] + 1e-5f);
        g_bnA[t] = inv;
        g_bnB[t] = bb[t & 63] * inv + bi[t] - me[t] * inv;
    }

    // Gate (threads 0..15, one per batch)
    if (t < NB) {
        int b = t;
        float lg[4];
        for (int e = 0; e < 4; ++e) {
            float s = gb[e];
            for (int c = 0; c < CIN; ++c) s += g_pooled[b * CIN + c] * gw[e * CIN + c];
            lg[e] = s;
        }
        float m = fmaxf(fmaxf(lg[0], lg[1]), fmaxf(lg[2], lg[3]));
        float p[4];
        float Z = 0.f;
        for (int e = 0; e < 4; ++e) { p[e] = expf(lg[e] - m); Z += p[e]; }
        for (int e = 0; e < 4; ++e) p[e] /= Z;
        int i0 = 0;
        for (int e = 1; e < 4; ++e) if (p[e] > p[i0]) i0 = e;   // strict >, lower idx wins ties
        int i1 = -1;
        for (int e = 0; e < 4; ++e) {
            if (e == i0) continue;
            if (i1 < 0 || p[e] > p[i1]) i1 = e;
        }
        float den = p[i0] + p[i1] + 1e-8f;
        g_selidx[b * 2 + 0] = i0; g_selwt[b * 2 + 0] = p[i0] / den;
        g_selidx[b * 2 + 1] = i1; g_selwt[b * 2 + 1] = p[i1] / den;
        s_idx[b * 2 + 0] = i0;
        s_idx[b * 2 + 1] = i1;
    }
    __syncthreads();
    if (t == 0) {
        // stable counting sort, heaviest expert (largest K) first
        int n = 0;
        for (int e = 3; e >= 0; --e)
            for (int z = 0; z < NB * 2; ++z)
                if (s_idx[z] == e) g_sched[n++] = z;
    }
}

// ---------------- launch #4: merged expert conv + BN + GELU, packed f32x2 FMA ---
// TAP-OUTER, PREDICATE-FREE MAINLOOP:
// 256 threads = 32(ow) x 4(cout-quarter:16 couts) x 2(row groups);
// each thread 4 oh-rows x 16 couts => 4x8 u64 acc (64 regs) -> 2 blocks/SM.
// For each (kh,kw) tap: boundary handled ONCE by selecting the x pointer
// (valid ? &x[...] : g_zero). Inner cin-chunk loop is pure
// LDG + pack + broadcast LDS.128 + 32xFFMA2 with no predicates/masks.
template <int E, int K, int D, int CHUNK, int WOFF>
__device__ __forceinline__ void conv_body(const float* __restrict__ xb,
                                          float* __restrict__ out,
                                          int z, int tid, float4* sw4) {
    const int pad = D * (K - 1) / 2;
    const int owl = tid & 31;
    const int chq = (tid >> 5) & 3;              // 4 groups of 16 couts
    const int ohq = tid >> 7;                    // 2 groups of 4 rows
    const int ow  = blockIdx.x * 32 + owl;
    const int oh0 = blockIdx.y * 8 + ohq * 4;    // 4 rows per thread
    const int ows = 2 * ow - pad;

    int ohs[4];
    unsigned rmask[4];
#pragma unroll
    for (int p = 0; p < 4; ++p) {
        ohs[p] = 2 * (oh0 + p) - pad;
        unsigned m = 0;
#pragma unroll
        for (int k = 0; k < K; ++k)
            if ((unsigned)(ohs[p] + D * k) < (unsigned)HW) m |= 1u << k;
        rmask[p] = m;
    }
    unsigned cmask = 0;
#pragma unroll
    for (int k = 0; k < K; ++k)
        if ((unsigned)(ows + D * k) < (unsigned)HW) cmask |= 1u << k;

    unsigned long long acc[4][8];
#pragma unroll
    for (int p = 0; p < 4; ++p)
#pragma unroll
        for (int r = 0; r < 8; ++r) acc[p][r] = 0ULL;

    float* sw = (float*)sw4;
    const float4* wsrc = (const float4*)(g_wT + WOFF);

    for (int cc = 0; cc < CIN; cc += CHUNK) {
        __syncthreads();
        for (int i = tid; i < CHUNK * K * K * 16; i += 256)
            sw4[i] = wsrc[cc * (K * K * 16) + i];
        __syncthreads();

        // base of this chunk's x planes
        const float* xc = xb + (size_t)cc * (HW * HW);

#pragma unroll 1
        for (int kh = 0; kh < K; ++kh) {
            const float* xrow[4];
            bool rv[4];
#pragma unroll
            for (int p = 0; p < 4; ++p) {
                xrow[p] = xc + (ohs[p] + D * kh) * HW + ows;   // may be wild; gated below
                rv[p] = (rmask[p] >> kh) & 1;
            }
#pragma unroll
            for (int kw = 0; kw < K; ++kw) {
                const bool cv = (cmask >> kw) & 1;
                // one pointer select per pixel per tap; g_zero covers cl*65536 offsets
                const float* xq[4];
#pragma unroll
                for (int p = 0; p < 4; ++p)
                    xq[p] = (rv[p] && cv) ? (xrow[p] + D * kw) : g_zero;
                const float* wk = sw + (kh * K + kw) * 64 + chq * 16;
                // ---- pure LDG + pack + LDS.128 + FFMA2 over the cin chunk ----
#pragma unroll
                for (int cl = 0; cl < CHUNK; ++cl) {
                    unsigned long long x2[4];
#pragma unroll
                    for (int p = 0; p < 4; ++p) {
                        float v = __ldg(xq[p] + cl * (HW * HW));
                        asm("mov.b64 %0, {%1, %1};" : "=l"(x2[p])
                            : "r"(__float_as_uint(v)));
                    }
                    const ulonglong2* wq =
                        (const ulonglong2*)(wk + cl * (K * K * 64));
#pragma unroll
                    for (int q = 0; q < 4; ++q) {
                        ulonglong2 wv = wq[q];
#pragma unroll
                        for (int p = 0; p < 4; ++p) {
                            asm("fma.rn.f32x2 %0, %1, %2, %0;"
                                : "+l"(acc[p][2 * q + 0]) : "l"(x2[p]), "l"(wv.x));
                            asm("fma.rn.f32x2 %0, %1, %2, %0;"
                                : "+l"(acc[p][2 * q + 1]) : "l"(x2[p]), "l"(wv.y));
                        }
                    }
                }
            }
        }
    }

    // epilogue: BN fold + exact GELU + gate weight; stores coalesced along ow
    const float wt = g_selwt[z];
    const int b = z >> 1, s = z & 1;
#pragma unroll
    for (int p = 0; p < 4; ++p) {
        float* ob = out + ((size_t)b * 128 + s * 64 + chq * 16) * (HO * HO)
                  + (oh0 + p) * HO + ow;
#pragma unroll
        for (int r = 0; r < 8; ++r) {
            unsigned u0, u1;
            asm("mov.b64 {%0, %1}, %2;" : "=r"(u0), "=r"(u1) : "l"(acc[p][r]));
            float v0 = __uint_as_float(u0);
            float v1 = __uint_as_float(u1);
            const int c0 = chq * 16 + 2 * r, c1 = c0 + 1;
            float y0 = v0 * g_bnA[E * 64 + c0] + g_bnB[E * 64 + c0];
            float y1 = v1 * g_bnA[E * 64 + c1] + g_bnB[E * 64 + c1];
            y0 = 0.5f * y0 * (1.f + erff(y0 * 0.70710678118654752f));
            y1 = 0.5f * y1 * (1.f + erff(y1 * 0.70710678118654752f));
            ob[(size_t)(2 * r) * (HO * HO)]     = y0 * wt;
            ob[(size_t)(2 * r + 1) * (HO * HO)] = y1 * wt;
        }
    }
}

__global__ void __launch_bounds__(256, 2)
conv_all_kernel(const float* __restrict__ x, float* __restrict__ out) {
    __shared__ float4 sw4[2592];   // max: E3 CHUNK=2 -> 2*81*64 floats = 41472 B
    const int z = g_sched[blockIdx.z];          // heavy-first schedule
    const int tid = threadIdx.x;
    const float* xb = x + (size_t)(z >> 1) * CIN * HW * HW;
    const int e = g_selidx[z];
    if (e == 0)      conv_body<0, 3, 1, 16, 0     >(xb, out, z, tid, sw4);
    else if (e == 1) conv_body<1, 5, 2, 4,  36864 >(xb, out, z, tid, sw4);
    else if (e == 2) conv_body<2, 7, 3, 2,  139264>(xb, out, z, tid, sw4);
    else             conv_body<3, 9, 4, 2,  339968>(xb, out, z, tid, sw4);
}

// ---------------- launch: exactly 4 launches, conv is #4 (ncu capture slot) -----
extern "C" void kernel_launch(void* const* d_in, const int* in_sizes, int n_in,
                              void* d_out, int out_size) {
    (void)in_sizes; (void)n_in; (void)out_size;
    const float* x   = (const float*)d_in[0];
    const float* w0  = (const float*)d_in[1];
    const float* b0  = (const float*)d_in[2];
    const float* w1  = (const float*)d_in[3];
    const float* b1  = (const float*)d_in[4];
    const float* w2  = (const float*)d_in[5];
    const float* b2  = (const float*)d_in[6];
    const float* w3  = (const float*)d_in[7];
    const float* b3  = (const float*)d_in[8];
    const float* bns = (const float*)d_in[9];
    const float* bnb = (const float*)d_in[10];
    const float* bnm = (const float*)d_in[11];
    const float* bnv = (const float*)d_in[12];
    const float* gw  = (const float*)d_in[13];
    const float* gb  = (const float*)d_in[14];
    float* out = (float*)d_out;

    pool_kernel<<<NB * CIN, 256>>>(x);                               // #1
    twk_all_kernel<<<(671744 + 255) / 256, 256>>>(w0, w1, w2, w3);   // #2
    gatebn_kernel<<<1, 256>>>(gw, gb, bns, bnb, bnm, bnv,
                              b0, b1, b2, b3);                       // #3
    dim3 grid(4, 16, NB * 2);  // 128/32 ow-tiles x 128/8 oh-tiles x (b,slot)
    conv_all_kernel<<<grid, 256>>>(x, out);                          // #4
}

// round 11
// speedup vs baseline: 1.4849x; 1.0836x over previous
#include <cuda_runtime.h>
#include <math.h>

#define CIN 64
#define HW  256
#define HO  128
#define NB  16

// ---------------- device scratch (no allocations allowed) ----------------
__device__ float g_pooled[NB * CIN];
__device__ int   g_selidx[NB * 2];
__device__ float g_selwt [NB * 2];
__device__ int   g_sched [NB * 2];   // block order: heavy experts first
__device__ float g_bnA[4 * 64];
__device__ float g_bnB[4 * 64];
// transposed weights [e][cin][kh][kw][cout], cout minor
// sizes: e0 36864, e1 102400, e2 200704, e3 331776 -> total 671744
__device__ float g_wT[671744];
// zero page: out-of-bounds taps point here (covers cl*65536 offsets, CHUNK<=16)
__device__ float g_zero[1048576];    // 4 MB, zero-initialized at module load

// ---------------- launch #1: global average pool, one block per (b,c) plane ----
__global__ void pool_kernel(const float* __restrict__ x) {
    __shared__ float red[256];
    int tid = threadIdx.x;
    const float4* xp = (const float4*)(x + (size_t)blockIdx.x * (HW * HW));
    float s = 0.f;
    for (int i = tid; i < HW * HW / 4; i += 256) {
        float4 v = xp[i];
        s += (v.x + v.y) + (v.z + v.w);
    }
    red[tid] = s;
    __syncthreads();
    for (int off = 128; off > 0; off >>= 1) {
        if (tid < off) red[tid] += red[tid + off];
        __syncthreads();
    }
    if (tid == 0) g_pooled[blockIdx.x] = red[0] * (1.f / (HW * HW));
}

// ---------------- launch #2: ALL weight transposes in one kernel ----------------
__device__ __forceinline__ void twk_one(const float* __restrict__ w, int off, int KK, int i) {
    int cout = i & 63;
    int row  = i >> 6;
    int cin  = row / KK;
    int kidx = row - cin * KK;
    g_wT[off + i] = w[(cout * 64 + cin) * KK + kidx];
}

__global__ void twk_all_kernel(const float* __restrict__ w0, const float* __restrict__ w1,
                               const float* __restrict__ w2, const float* __restrict__ w3) {
    int i = blockIdx.x * 256 + threadIdx.x;
    if (i < 36864)       twk_one(w0, 0,      9,  i);
    else if (i < 139264) twk_one(w1, 36864,  25, i - 36864);
    else if (i < 339968) twk_one(w2, 139264, 49, i - 139264);
    else if (i < 671744) twk_one(w3, 339968, 81, i - 339968);
}

// ---------------- launch #3: gate (softmax + top-2 + schedule) AND bn fold ------
__global__ void gatebn_kernel(const float* __restrict__ gw, const float* __restrict__ gb,
                              const float* __restrict__ sc, const float* __restrict__ bi,
                              const float* __restrict__ me, const float* __restrict__ va,
                              const float* __restrict__ b0, const float* __restrict__ b1,
                              const float* __restrict__ b2, const float* __restrict__ b3) {
    __shared__ int s_idx[NB * 2];
    int t = threadIdx.x;

    // BN fold: y = conv*A + B  (256 threads = 4 experts x 64 couts)
    {
        const float* bb = (t < 64) ? b0 : (t < 128) ? b1 : (t < 192) ? b2 : b3;
        float inv = sc[t] * rsqrtf(va[t] + 1e-5f);
        g_bnA[t] = inv;
        g_bnB[t] = bb[t & 63] * inv + bi[t] - me[t] * inv;
    }

    // Gate (threads 0..15, one per batch)
    if (t < NB) {
        int b = t;
        float lg[4];
        for (int e = 0; e < 4; ++e) {
            float s = gb[e];
            for (int c = 0; c < CIN; ++c) s += g_pooled[b * CIN + c] * gw[e * CIN + c];
            lg[e] = s;
        }
        float m = fmaxf(fmaxf(lg[0], lg[1]), fmaxf(lg[2], lg[3]));
        float p[4];
        float Z = 0.f;
        for (int e = 0; e < 4; ++e) { p[e] = expf(lg[e] - m); Z += p[e]; }
        for (int e = 0; e < 4; ++e) p[e] /= Z;
        int i0 = 0;
        for (int e = 1; e < 4; ++e) if (p[e] > p[i0]) i0 = e;   // strict >, lower idx wins ties
        int i1 = -1;
        for (int e = 0; e < 4; ++e) {
            if (e == i0) continue;
            if (i1 < 0 || p[e] > p[i1]) i1 = e;
        }
        float den = p[i0] + p[i1] + 1e-8f;
        g_selidx[b * 2 + 0] = i0; g_selwt[b * 2 + 0] = p[i0] / den;
        g_selidx[b * 2 + 1] = i1; g_selwt[b * 2 + 1] = p[i1] / den;
        s_idx[b * 2 + 0] = i0;
        s_idx[b * 2 + 1] = i1;
    }
    __syncthreads();
    if (t == 0) {
        // stable counting sort, heaviest expert (largest K) first
        int n = 0;
        for (int e = 3; e >= 0; --e)
            for (int z = 0; z < NB * 2; ++z)
                if (s_idx[z] == e) g_sched[n++] = z;
    }
}

// ---------------- launch #4: merged expert conv + BN + GELU, packed f32x2 FMA ---
// TAP-OUTER, PREDICATE-FREE MAINLOOP, BIG-CHUNK DYNAMIC SMEM:
// 256 threads = 32(ow) x 4(cout-quarter:16 couts) x 2(row groups);
// each thread 4 oh-rows x 16 couts => 4x8 u64 acc (64 regs) -> 2 blocks/SM.
// Boundary handled ONCE per tap by pointer select (valid ? &x[...] : g_zero);
// inner cin-chunk loop is pure LDG + pack + broadcast LDS.128 + 32xFFMA2.
// CHUNK raised (E1:8, E2:4, E3:4) via 83KB dynamic smem: fewer barriers,
// better tap-overhead amortization, longer pipelined FFMA2 streams.
template <int E, int K, int D, int CHUNK, int WOFF>
__device__ __forceinline__ void conv_body(const float* __restrict__ xb,
                                          float* __restrict__ out,
                                          int z, int tid, float4* sw4) {
    const int pad = D * (K - 1) / 2;
    const int owl = tid & 31;
    const int chq = (tid >> 5) & 3;              // 4 groups of 16 couts
    const int ohq = tid >> 7;                    // 2 groups of 4 rows
    const int ow  = blockIdx.x * 32 + owl;
    const int oh0 = blockIdx.y * 8 + ohq * 4;    // 4 rows per thread
    const int ows = 2 * ow - pad;

    int ohs[4];
    unsigned rmask[4];
#pragma unroll
    for (int p = 0; p < 4; ++p) {
        ohs[p] = 2 * (oh0 + p) - pad;
        unsigned m = 0;
#pragma unroll
        for (int k = 0; k < K; ++k)
            if ((unsigned)(ohs[p] + D * k) < (unsigned)HW) m |= 1u << k;
        rmask[p] = m;
    }
    unsigned cmask = 0;
#pragma unroll
    for (int k = 0; k < K; ++k)
        if ((unsigned)(ows + D * k) < (unsigned)HW) cmask |= 1u << k;

    unsigned long long acc[4][8];
#pragma unroll
    for (int p = 0; p < 4; ++p)
#pragma unroll
        for (int r = 0; r < 8; ++r) acc[p][r] = 0ULL;

    float* sw = (float*)sw4;
    const float4* wsrc = (const float4*)(g_wT + WOFF);

    for (int cc = 0; cc < CIN; cc += CHUNK) {
        __syncthreads();
        for (int i = tid; i < CHUNK * K * K * 16; i += 256)
            sw4[i] = wsrc[cc * (K * K * 16) + i];
        __syncthreads();

        // base of this chunk's x planes
        const float* xc = xb + (size_t)cc * (HW * HW);

#pragma unroll 1
        for (int kh = 0; kh < K; ++kh) {
            const float* xrow[4];
            bool rv[4];
#pragma unroll
            for (int p = 0; p < 4; ++p) {
                xrow[p] = xc + (ohs[p] + D * kh) * HW + ows;   // may be wild; gated below
                rv[p] = (rmask[p] >> kh) & 1;
            }
#pragma unroll
            for (int kw = 0; kw < K; ++kw) {
                const bool cv = (cmask >> kw) & 1;
                // one pointer select per pixel per tap; g_zero covers cl*65536 offsets
                const float* xq[4];
#pragma unroll
                for (int p = 0; p < 4; ++p)
                    xq[p] = (rv[p] && cv) ? (xrow[p] + D * kw) : g_zero;
                const float* wk = sw + (kh * K + kw) * 64 + chq * 16;
                // ---- pure LDG + pack + LDS.128 + FFMA2 over the cin chunk ----
#pragma unroll
                for (int cl = 0; cl < CHUNK; ++cl) {
                    unsigned long long x2[4];
#pragma unroll
                    for (int p = 0; p < 4; ++p) {
                        float v = __ldg(xq[p] + cl * (HW * HW));
                        asm("mov.b64 %0, {%1, %1};" : "=l"(x2[p])
                            : "r"(__float_as_uint(v)));
                    }
                    const ulonglong2* wq =
                        (const ulonglong2*)(wk + cl * (K * K * 64));
#pragma unroll
                    for (int q = 0; q < 4; ++q) {
                        ulonglong2 wv = wq[q];
#pragma unroll
                        for (int p = 0; p < 4; ++p) {
                            asm("fma.rn.f32x2 %0, %1, %2, %0;"
                                : "+l"(acc[p][2 * q + 0]) : "l"(x2[p]), "l"(wv.x));
                            asm("fma.rn.f32x2 %0, %1, %2, %0;"
                                : "+l"(acc[p][2 * q + 1]) : "l"(x2[p]), "l"(wv.y));
                        }
                    }
                }
            }
        }
    }

    // epilogue: BN fold + exact GELU + gate weight; stores coalesced along ow
    const float wt = g_selwt[z];
    const int b = z >> 1, s = z & 1;
#pragma unroll
    for (int p = 0; p < 4; ++p) {
        float* ob = out + ((size_t)b * 128 + s * 64 + chq * 16) * (HO * HO)
                  + (oh0 + p) * HO + ow;
#pragma unroll
        for (int r = 0; r < 8; ++r) {
            unsigned u0, u1;
            asm("mov.b64 {%0, %1}, %2;" : "=r"(u0), "=r"(u1) : "l"(acc[p][r]));
            float v0 = __uint_as_float(u0);
            float v1 = __uint_as_float(u1);
            const int c0 = chq * 16 + 2 * r, c1 = c0 + 1;
            float y0 = v0 * g_bnA[E * 64 + c0] + g_bnB[E * 64 + c0];
            float y1 = v1 * g_bnA[E * 64 + c1] + g_bnB[E * 64 + c1];
            y0 = 0.5f * y0 * (1.f + erff(y0 * 0.70710678118654752f));
            y1 = 0.5f * y1 * (1.f + erff(y1 * 0.70710678118654752f));
            ob[(size_t)(2 * r) * (HO * HO)]     = y0 * wt;
            ob[(size_t)(2 * r + 1) * (HO * HO)] = y1 * wt;
        }
    }
}

// dynamic smem: max = E3 CHUNK=4 -> 4*81*64 floats = 82944 bytes
#define CONV_SMEM_BYTES 82944

__global__ void __launch_bounds__(256, 2)
conv_all_kernel(const float* __restrict__ x, float* __restrict__ out) {
    extern __shared__ float4 sw4[];
    const int z = g_sched[blockIdx.z];          // heavy-first schedule
    const int tid = threadIdx.x;
    const float* xb = x + (size_t)(z >> 1) * CIN * HW * HW;
    const int e = g_selidx[z];
    if (e == 0)      conv_body<0, 3, 1, 16, 0     >(xb, out, z, tid, sw4);
    else if (e == 1) conv_body<1, 5, 2, 8,  36864 >(xb, out, z, tid, sw4);
    else if (e == 2) conv_body<2, 7, 3, 4,  139264>(xb, out, z, tid, sw4);
    else             conv_body<3, 9, 4, 4,  339968>(xb, out, z, tid, sw4);
}

// ---------------- launch: exactly 4 launches, conv is #4 (ncu capture slot) -----
extern "C" void kernel_launch(void* const* d_in, const int* in_sizes, int n_in,
                              void* d_out, int out_size) {
    (void)in_sizes; (void)n_in; (void)out_size;
    const float* x   = (const float*)d_in[0];
    const float* w0  = (const float*)d_in[1];
    const float* b0  = (const float*)d_in[2];
    const float* w1  = (const float*)d_in[3];
    const float* b1  = (const float*)d_in[4];
    const float* w2  = (const float*)d_in[5];
    const float* b2  = (const float*)d_in[6];
    const float* w3  = (const float*)d_in[7];
    const float* b3  = (const float*)d_in[8];
    const float* bns = (const float*)d_in[9];
    const float* bnb = (const float*)d_in[10];
    const float* bnm = (const float*)d_in[11];
    const float* bnv = (const float*)d_in[12];
    const float* gw  = (const float*)d_in[13];
    const float* gb  = (const float*)d_in[14];
    float* out = (float*)d_out;

    static int s_attr_set = 0;
    if (!s_attr_set) {
        cudaFuncSetAttribute(conv_all_kernel,
                             cudaFuncAttributeMaxDynamicSharedMemorySize,
                             CONV_SMEM_BYTES);
        s_attr_set = 1;
    }

    pool_kernel<<<NB * CIN, 256>>>(x);                               // #1
    twk_all_kernel<<<(671744 + 255) / 256, 256>>>(w0, w1, w2, w3);   // #2
    gatebn_kernel<<<1, 256>>>(gw, gb, bns, bnb, bnm, bnv,
                              b0, b1, b2, b3);                       // #3
    dim3 grid(4, 16, NB * 2);  // 128/32 ow-tiles x 128/8 oh-tiles x (b,slot)
    conv_all_kernel<<<grid, 256, CONV_SMEM_BYTES>>>(x, out);         // #4
}